// round 9
// baseline (speedup 1.0000x reference)
#include <cuda_runtime.h>
#include <cuda_bf16.h>

typedef unsigned int       u32;
typedef unsigned long long u64;

#define BSZ      64
#define ENC_IN   64
#define ENC_HID  256
#define NNODES   2048
#define GHD      128
#define JTOT     (NNODES * GHD)      // 262144
#define LN_EPS   1e-5f

#define N_ENC_BLK NNODES             // 2048 (one node per enc block)
#define N_GCN_BLK (17 * BSZ)         // 1088
#define N_MEGA    (3 * N_GCN_BLK)    // 3264: pattern [enc enc gcn]

// ---------------- scratch (device globals: allocation-guard safe) ----------
__device__ float g_h1[BSZ * ENC_HID];                  // [m][k] h1 rows
__device__ float g_buf0[(size_t)BSZ * NNODES * GHD];   // enc output
// Wg1 transposed [n][k] bf16 hi/lo image, row stride 136 halfs (= 68 u32)
__device__ __align__(16) u32 g_BH[GHD * 68];
__device__ __align__(16) u32 g_BL[GHD * 68];
// layer-2 collapse vectors: w2o = Wg2 @ Wout; gw = g2*w2o; K = {sum gw, sum b2*w2o}
__device__ float g_gw[GHD];
__device__ float g_K[2];
// per-node completion flags + consumer ticket for producer/consumer overlap
__device__ int g_flag[NNODES];
__device__ int g_ticket;

extern __shared__ __align__(1024) char dynsm[];

// ---------------- helpers ---------------------------------------------------
__device__ __forceinline__ u32 smem_u32(const void* p) {
    u32 a;
    asm("{ .reg .u64 t; cvta.to.shared.u64 t, %1; cvt.u32.u64 %0, t; }"
        : "=r"(a) : "l"(p));
    return a;
}
__device__ __forceinline__ void ldsm4(u32* r, u32 a) {
    asm volatile("ldmatrix.sync.aligned.m8n8.x4.shared.b16 {%0,%1,%2,%3}, [%4];"
                 : "=r"(r[0]), "=r"(r[1]), "=r"(r[2]), "=r"(r[3]) : "r"(a));
}
__device__ __forceinline__ void ldsm4t(u32* r, u32 a) {
    asm volatile("ldmatrix.sync.aligned.m8n8.x4.trans.shared.b16 {%0,%1,%2,%3}, [%4];"
                 : "=r"(r[0]), "=r"(r[1]), "=r"(r[2]), "=r"(r[3]) : "r"(a));
}
__device__ __forceinline__ void mma16816(float* c, const u32* a, u32 b0, u32 b1) {
    asm volatile(
        "mma.sync.aligned.m16n8k16.row.col.f32.bf16.bf16.f32 "
        "{%0,%1,%2,%3}, {%4,%5,%6,%7}, {%8,%9}, {%0,%1,%2,%3};"
        : "+f"(c[0]), "+f"(c[1]), "+f"(c[2]), "+f"(c[3])
        : "r"(a[0]), "r"(a[1]), "r"(a[2]), "r"(a[3]), "r"(b0), "r"(b1));
}
__device__ __forceinline__ void split2(float a, float b, u32& hi, u32& lo) {
    __nv_bfloat162 h = __floats2bfloat162_rn(a, b);
    float ha = __bfloat162float(h.x), hb = __bfloat162float(h.y);
    __nv_bfloat162 l = __floats2bfloat162_rn(a - ha, b - hb);
    hi = *reinterpret_cast<u32*>(&h);
    lo = *reinterpret_cast<u32*>(&l);
}

// ===========================================================================
// K_INIT (one launch): blocks 0..63 -> h1 = relu(x@W1+b1) + flag reset;
//   block 64 -> Wg1 bf16 image + ticket reset; block 65 -> collapse vectors.
// ===========================================================================
__global__ void k_init(const float* __restrict__ x,
                       const float* __restrict__ W1,
                       const float* __restrict__ b1,
                       const float* __restrict__ Wg1,
                       const float* __restrict__ Wg2,
                       const float* __restrict__ Wout,
                       const float* __restrict__ g2,
                       const float* __restrict__ b2ln) {
    const int bx = blockIdx.x;
    const int j  = threadIdx.x;
    if (bx < 64) {
        if (j < 32) g_flag[bx * 32 + j] = 0;
        __shared__ float sx[ENC_IN];
        if (j < ENC_IN) sx[j] = x[bx * ENC_IN + j];
        __syncthreads();
        float acc = b1[j];
#pragma unroll
        for (int k = 0; k < ENC_IN; k++)
            acc = fmaf(sx[k], W1[k * ENC_HID + j], acc);
        g_h1[bx * ENC_HID + j] = fmaxf(acc, 0.0f);
    } else if (bx == 64) {
        if (j == 0) g_ticket = 0;
        if (j < GHD) {
            for (int k = 0; k < GHD; k += 2) {
                u32 hi, lo;
                split2(Wg1[k * GHD + j], Wg1[(k + 1) * GHD + j], hi, lo);
                g_BH[j * 68 + (k >> 1)] = hi;
                g_BL[j * 68 + (k >> 1)] = lo;
            }
        }
    } else {
        __shared__ float sr1[GHD], sr2[GHD];
        if (j < GHD) {
            float w2o = 0.0f;
            for (int d = 0; d < GHD; d++)
                w2o = fmaf(Wg2[j * GHD + d], Wout[d], w2o);
            float gwv = g2[j] * w2o;
            g_gw[j] = gwv;
            sr1[j] = gwv;
            sr2[j] = b2ln[j] * w2o;
        }
        __syncthreads();
        if (j == 0) {
            float k1 = 0.0f, k2 = 0.0f;
            for (int i = 0; i < GHD; i++) { k1 += sr1[i]; k2 += sr2[i]; }
            g_K[0] = k1;
            g_K[1] = k2;
        }
    }
}

// ===========================================================================
// K_MEGA: interleaved roles, pattern [enc enc gcn] by blockIdx.x % 3.
//  enc role: node e = (bx/3)*2 + bx%3 (skip if >=2048); computes
//            enc(:, e, :) = h1 @ W2[:, e*128..] + b2; sets g_flag[e].
//  gcn role: dynamic ticket -> (tile, batch); waits on the tile's node flags,
//            then fused GCN layer-1 GEMM + collapsed layer-2 + projection.
// ===========================================================================
// enc-role smem offsets
#define ESB       528
#define EBB       272
#define E_AHI     0
#define E_ALO     33792
#define E_BHI     67584
#define E_BLO     76288
// gcn-role smem offsets
#define GSB       272
#define G_AHI     0
#define G_ALO     34816
#define G_RB      69632                    // B-half hi staging / C tile
#define G_RLO     87040                    // B-half lo staging
#define G_SMEM    104448

__global__ __launch_bounds__(256, 2) void k_mega(const float* __restrict__ W2,
                                                 const float* __restrict__ b2,
                                                 const float* __restrict__ Ah,
                                                 const float* __restrict__ g1,
                                                 const float* __restrict__ bb1,
                                                 const float* __restrict__ Wout,
                                                 const float* __restrict__ bout,
                                                 float* __restrict__ proj) {
    const int tid = threadIdx.x;
    const int L   = tid & 31;
    const int w   = tid >> 5;
    const u32 sb  = smem_u32(dynsm);

    if (blockIdx.x % 3 != 2) {
        // ================= enc role =================
        const int e = (blockIdx.x / 3) * 2 + (blockIdx.x % 3);
        if (e >= N_ENC_BLK) return;
        const int j0 = e * 128;

        // ---- stage A = h1 (bf16 hi/lo), full K=256 ----
        for (int i = tid; i < 4096; i += 256) {
            int row = i >> 6, c4 = i & 63;
            float4 v = *(const float4*)&g_h1[row * ENC_HID + c4 * 4];
            u32 h0, l0, h1, l1;
            split2(v.x, v.y, h0, l0);
            split2(v.z, v.w, h1, l1);
            *(uint2*)(dynsm + E_AHI + row * ESB + c4 * 8) = make_uint2(h0, h1);
            *(uint2*)(dynsm + E_ALO + row * ESB + c4 * 8) = make_uint2(l0, l1);
        }

        const int mw = w & 1, nw = w >> 1;
        const int R0 = mw * 32, N0 = nw * 32;
        const u32 arow = (u32)(L & 15);
        const u32 kcol = (u32)((L >> 4) << 3);
        const u32 brow = (u32)((L & 7) + ((L >> 3) & 1) * 8);
        const u32 bcol = (u32)((L >> 4) << 3);

        float acc[2][4][4];
#pragma unroll
        for (int mt = 0; mt < 2; mt++)
#pragma unroll
            for (int j = 0; j < 4; j++)
#pragma unroll
                for (int c = 0; c < 4; c++) acc[mt][j][c] = 0.0f;

        float4 pf[4];
#pragma unroll
        for (int t = 0; t < 4; t++) {
            int i = tid + t * 256;
            int row = i >> 5, c4 = i & 31;
            pf[t] = *(const float4*)&W2[(size_t)row * JTOT + j0 + c4 * 4];
        }

        for (int kp = 0; kp < 8; kp++) {
            __syncthreads();
#pragma unroll
            for (int t = 0; t < 4; t++) {
                int i = tid + t * 256;
                int row = i >> 5, c4 = i & 31;
                u32 h0, l0, h1, l1;
                split2(pf[t].x, pf[t].y, h0, l0);
                split2(pf[t].z, pf[t].w, h1, l1);
                *(uint2*)(dynsm + E_BHI + row * EBB + c4 * 8) = make_uint2(h0, h1);
                *(uint2*)(dynsm + E_BLO + row * EBB + c4 * 8) = make_uint2(l0, l1);
            }
            __syncthreads();
            if (kp < 7) {
#pragma unroll
                for (int t = 0; t < 4; t++) {
                    int i = tid + t * 256;
                    int row = i >> 5, c4 = i & 31;
                    pf[t] = *(const float4*)&W2[(size_t)((kp + 1) * 32 + row) * JTOT +
                                                j0 + c4 * 4];
                }
            }

#pragma unroll
            for (int p = 0; p < 3; p++) {
                const u32 aOff = (p < 2) ? E_AHI : E_ALO;
                const u32 bOff = (p == 1) ? E_BLO : E_BHI;
#pragma unroll
                for (int ks = 0; ks < 2; ks++) {
                    u32 a0[4], a1[4];
                    u32 ka = (u32)((kp * 32 + ks * 16 + kcol) * 2);
                    ldsm4(a0, sb + aOff + (R0 + arow) * ESB + ka);
                    ldsm4(a1, sb + aOff + (R0 + 16 + arow) * ESB + ka);
                    u32 bf[2][4];
                    u32 kb = (u32)((ks * 16 + brow) * EBB);
#pragma unroll
                    for (int nt = 0; nt < 2; nt++)
                        ldsm4t(bf[nt], sb + bOff + kb + (N0 + nt * 16 + bcol) * 2);
#pragma unroll
                    for (int j = 0; j < 4; j++) {
                        u32 b0 = bf[j >> 1][(j & 1) * 2];
                        u32 b1 = bf[j >> 1][(j & 1) * 2 + 1];
                        mma16816(acc[0][j], a0, b0, b1);
                        mma16816(acc[1][j], a1, b0, b1);
                    }
                }
            }
        }

#pragma unroll
        for (int mt = 0; mt < 2; mt++) {
            int m = R0 + mt * 16 + (L >> 2);
#pragma unroll
            for (int j = 0; j < 4; j++) {
                int n = j0 + N0 + j * 8 + (L & 3) * 2;
                float b20 = __ldg(&b2[n]), b21 = __ldg(&b2[n + 1]);
                *(float2*)&g_buf0[(size_t)m * JTOT + n] =
                    make_float2(acc[mt][j][0] + b20, acc[mt][j][1] + b21);
                *(float2*)&g_buf0[(size_t)(m + 8) * JTOT + n] =
                    make_float2(acc[mt][j][2] + b20, acc[mt][j][3] + b21);
            }
        }

        // ---- publish: node e is complete ----
        __threadfence();
        __syncthreads();
        if (tid == 0) ((volatile int*)g_flag)[e] = 1;
        return;
    }

    // ================= gcn role =================
    __shared__ float sAp[128], sAn[128];
    __shared__ float sG1[128], sB1[128], sWo[128], sGw[128];
    __shared__ float sP[128][4];
    __shared__ float sT[128], sU[128];
    __shared__ int s_t;

    if (tid == 0) s_t = atomicAdd(&g_ticket, 1);
    __syncthreads();
    const int t0 = s_t;
    const int nt = t0 >> 6;                // tile (in readiness order)
    const int b  = t0 & 63;
    const int n0 = nt * 124;               // staged row r <-> gi = n0 - 2 + r

    if (tid < 128) {
        sG1[tid] = g1[tid];
        sB1[tid] = bb1[tid];
        sWo[tid] = Wout[tid];
        sGw[tid] = g_gw[tid];
        int gi = n0 - 2 + tid;
        sAp[tid] = (gi >= 1 && gi < NNODES) ? Ah[(size_t)gi * NNODES + gi - 1] : 0.0f;
        sAn[tid] = (gi >= 0 && gi < NNODES - 1) ? Ah[(size_t)gi * NNODES + gi + 1] : 0.0f;
    }

    // ---- stage B half 0 (no dependency on enc output) ----
    {
        uint4* dh = (uint4*)(dynsm + G_RB);
        uint4* dl = (uint4*)(dynsm + G_RLO);
        for (int i = tid; i < 1088; i += 256) {
            dh[i] = ((const uint4*)g_BH)[i];
            dl[i] = ((const uint4*)g_BL)[i];
        }
    }

    // ---- wait for the nodes this tile reads ----
    if (tid < 128) {
        int gi = min(NNODES - 1, max(0, n0 - 2 + tid));
        while (((volatile int*)g_flag)[gi] == 0) __nanosleep(128);
    }
    __threadfence();
    __syncthreads();

    // ---- LN1 + bf16 split -> A tiles (warp w owns rows {w+8t}) ----
    const int c0 = 2 * L, c2 = 64 + 2 * L;
#pragma unroll 4
    for (int t = 0; t < 16; t++) {
        int row = w + 8 * t;
        int gi  = min(NNODES - 1, max(0, n0 - 2 + row));
        const float* p = &g_buf0[((size_t)b * NNODES + gi) * GHD + c0];
        float2 v0 = *(const float2*)p;
        float2 v1 = *(const float2*)(p + 64);
        float s = v0.x + v0.y + v1.x + v1.y;
        float q = v0.x * v0.x + v0.y * v0.y + v1.x * v1.x + v1.y * v1.y;
#pragma unroll
        for (int o = 16; o; o >>= 1) {
            s += __shfl_xor_sync(0xFFFFFFFFu, s, o);
            q += __shfl_xor_sync(0xFFFFFFFFu, q, o);
        }
        float mu   = s * (1.0f / GHD);
        float rstd = rsqrtf(fmaxf(q * (1.0f / GHD) - mu * mu, 0.0f) + LN_EPS);
        float f0 = (v0.x - mu) * rstd * sG1[c0] + sB1[c0];
        float f1 = (v0.y - mu) * rstd * sG1[c0 + 1] + sB1[c0 + 1];
        float f2 = (v1.x - mu) * rstd * sG1[c2] + sB1[c2];
        float f3 = (v1.y - mu) * rstd * sG1[c2 + 1] + sB1[c2 + 1];
        u32 h0, l0, h1, l1;
        split2(f0, f1, h0, l0);
        split2(f2, f3, h1, l1);
        *(u32*)(dynsm + G_AHI + row * GSB + L * 4)       = h0;
        *(u32*)(dynsm + G_AHI + row * GSB + 128 + L * 4) = h1;
        *(u32*)(dynsm + G_ALO + row * GSB + L * 4)       = l0;
        *(u32*)(dynsm + G_ALO + row * GSB + 128 + L * 4) = l1;
    }
    __syncthreads();

    const int mw = w & 3, nh = w >> 2;
    const int R0 = mw * 32, N0 = nh * 32;
    const u32 arow = (u32)(L & 15);
    const u32 kcol = (u32)((L >> 4) << 3);
    float* sC = (float*)(dynsm + G_RB);
    const float K1 = g_K[0], K2 = g_K[1];

    for (int h = 0; h < 2; h++) {
        if (h) {
            uint4* dh = (uint4*)(dynsm + G_RB);
            uint4* dl = (uint4*)(dynsm + G_RLO);
            for (int i = tid; i < 1088; i += 256) {
                dh[i] = ((const uint4*)g_BH)[1088 + i];
                dl[i] = ((const uint4*)g_BL)[1088 + i];
            }
            __syncthreads();
        }

        // ---- MMA: 128M x 64N, 3-pass bf16 split (warp tile 32x32) ----
        float acc[2][4][4];
#pragma unroll
        for (int mt = 0; mt < 2; mt++)
#pragma unroll
            for (int j = 0; j < 4; j++)
#pragma unroll
                for (int c = 0; c < 4; c++) acc[mt][j][c] = 0.0f;

#pragma unroll
        for (int p = 0; p < 3; p++) {
            const u32 aOff = (p < 2) ? G_AHI : G_ALO;
            const u32 bOff = (p == 1) ? (u32)G_RLO : (u32)G_RB;
#pragma unroll
            for (int ks = 0; ks < 8; ks++) {
                u32 kb = (u32)((ks * 16 + kcol) * 2);
                u32 a0[4], a1[4];
                ldsm4(a0, sb + aOff + (R0 + arow) * GSB + kb);
                ldsm4(a1, sb + aOff + (R0 + 16 + arow) * GSB + kb);
                u32 bf[2][4];
#pragma unroll
                for (int nth = 0; nth < 2; nth++)
                    ldsm4(bf[nth], sb + bOff + (N0 + nth * 16 + arow) * GSB + kb);
#pragma unroll
                for (int j = 0; j < 4; j++) {
                    u32 b0 = bf[j >> 1][(j & 1)];
                    u32 b1 = bf[j >> 1][(j & 1) + 2];
                    mma16816(acc[0][j], a0, b0, b1);
                    mma16816(acc[1][j], a1, b0, b1);
                }
            }
        }
        __syncthreads();

        // ---- C frags -> sC ----
#pragma unroll
        for (int mt = 0; mt < 2; mt++) {
            int m = R0 + mt * 16 + (L >> 2);
#pragma unroll
            for (int j = 0; j < 4; j++) {
                int n = N0 + j * 8 + (L & 3) * 2;
                *(float2*)&sC[m * 68 + n] =
                    make_float2(acc[mt][j][0], acc[mt][j][1]);
                *(float2*)&sC[(m + 8) * 68 + n] =
                    make_float2(acc[mt][j][2], acc[mt][j][3]);
            }
        }
        __syncthreads();

        // ---- dot pass: out1 cols of this half -> 4 partial dots per row ----
        const int cg = h * 64 + 2 * L;
#pragma unroll 2
        for (int t = 0; t < 16; t++) {
            int row = w + 8 * t;
            if (row < 1 || row > 126) continue;
            int gi = min(NNODES - 1, max(0, n0 - 2 + row));
            float2 iv = *(const float2*)&g_buf0[((size_t)b * NNODES + gi) * GHD + cg];
            float2 wp = *(const float2*)&sC[(row - 1) * 68 + 2 * L];
            float2 wn = *(const float2*)&sC[(row + 1) * 68 + 2 * L];
            float ap = sAp[row], an = sAn[row];
            float o0 = fmaf(an, wn.x, fmaf(ap, wp.x, iv.x));
            float o1 = fmaf(an, wn.y, fmaf(ap, wp.y, iv.y));
            float sv = o0 + o1;
            float sq = o0 * o0 + o1 * o1;
            float st = o0 * sWo[cg] + o1 * sWo[cg + 1];
            float sg = o0 * sGw[cg] + o1 * sGw[cg + 1];
#pragma unroll
            for (int o = 16; o; o >>= 1) {
                sv += __shfl_xor_sync(0xFFFFFFFFu, sv, o);
                sq += __shfl_xor_sync(0xFFFFFFFFu, sq, o);
                st += __shfl_xor_sync(0xFFFFFFFFu, st, o);
                sg += __shfl_xor_sync(0xFFFFFFFFu, sg, o);
            }
            if (L == 0) {
                if (h == 0) {
                    sP[row][0] = sv; sP[row][1] = sq;
                    sP[row][2] = st; sP[row][3] = sg;
                } else {
                    sv += sP[row][0];
                    sq += sP[row][1];
                    st += sP[row][2];
                    sg += sP[row][3];
                    float mu   = sv * (1.0f / GHD);
                    float rstd = rsqrtf(fmaxf(sq * (1.0f / GHD) - mu * mu, 0.0f) +
                                        LN_EPS);
                    sT[row] = st;
                    sU[row] = rstd * (sg - mu * K1) + K2;
                }
            }
        }
        __syncthreads();
    }

    // ---- final: rows 2..125 -> proj ----
    if (tid < 124) {
        int row = tid + 2;
        int gi  = n0 + tid;
        if (gi < NNODES) {
            float f = sT[row] + sAp[row] * sU[row - 1] + sAn[row] * sU[row + 1] +
                      bout[0];
            proj[b * NNODES + gi] = f;
        }
    }
}

// ===========================================================================
extern "C" void kernel_launch(void* const* d_in, const int* in_sizes, int n_in,
                              void* d_out, int out_size) {
    const float* x    = (const float*)d_in[0];
    const float* Ah   = (const float*)d_in[1];
    const float* W1   = (const float*)d_in[2];
    const float* b1   = (const float*)d_in[3];
    const float* W2   = (const float*)d_in[4];
    const float* b2   = (const float*)d_in[5];
    const float* Wg1  = (const float*)d_in[6];
    const float* Wg2  = (const float*)d_in[7];
    const float* g1   = (const float*)d_in[8];
    const float* bb1  = (const float*)d_in[9];
    const float* g2   = (const float*)d_in[10];
    const float* bb2  = (const float*)d_in[11];
    const float* Wout = (const float*)d_in[12];
    const float* bout = (const float*)d_in[13];
    float* out = (float*)d_out;

    cudaFuncSetAttribute(k_mega, cudaFuncAttributeMaxDynamicSharedMemorySize,
                         G_SMEM);

    k_init<<<66, ENC_HID>>>(x, W1, b1, Wg1, Wg2, Wout, g2, bb2);
    k_mega<<<N_MEGA, 256, G_SMEM>>>(W2, b2, Ah, g1, bb1, Wout, bout, out);
}

// round 10
// speedup vs baseline: 1.2797x; 1.2797x over previous
#include <cuda_runtime.h>
#include <cuda_bf16.h>

typedef unsigned int       u32;
typedef unsigned long long u64;

#define BSZ      64
#define ENC_IN   64
#define ENC_HID  256
#define NNODES   2048
#define GHD      128
#define JTOT     (NNODES * GHD)      // 262144
#define LN_EPS   1e-5f

#define N_ENC_BLK NNODES             // 2048 (one node per enc block)
#define N_GCN_BLK (17 * BSZ)         // 1088

// ---------------- scratch (device globals: allocation-guard safe) ----------
__device__ float g_h1[BSZ * ENC_HID];                  // [m][k] h1 rows
__device__ float g_buf0[(size_t)BSZ * NNODES * GHD];   // enc output
// A (=h1) bf16 hi/lo smem-image, row stride 528B (132 u32), 64 rows
__device__ __align__(16) u32 g_AH[64 * 132];
__device__ __align__(16) u32 g_AL[64 * 132];
// Wg1 transposed [n][k] bf16 hi/lo image, row stride 136 halfs (= 68 u32)
__device__ __align__(16) u32 g_BH[GHD * 68];
__device__ __align__(16) u32 g_BL[GHD * 68];
// layer-2 collapse: w2o = Wg2 @ Wout; gw = g2*w2o; K = {sum gw, sum b2*w2o}
__device__ float g_gw[GHD];
__device__ float g_K[2];
// per-node completion flags for producer/consumer safety
__device__ int g_flag[NNODES];

extern __shared__ __align__(1024) char dynsm[];

// ---------------- helpers ---------------------------------------------------
__device__ __forceinline__ u32 smem_u32(const void* p) {
    u32 a;
    asm("{ .reg .u64 t; cvta.to.shared.u64 t, %1; cvt.u32.u64 %0, t; }"
        : "=r"(a) : "l"(p));
    return a;
}
__device__ __forceinline__ void ldsm4(u32* r, u32 a) {
    asm volatile("ldmatrix.sync.aligned.m8n8.x4.shared.b16 {%0,%1,%2,%3}, [%4];"
                 : "=r"(r[0]), "=r"(r[1]), "=r"(r[2]), "=r"(r[3]) : "r"(a));
}
__device__ __forceinline__ void ldsm4t(u32* r, u32 a) {
    asm volatile("ldmatrix.sync.aligned.m8n8.x4.trans.shared.b16 {%0,%1,%2,%3}, [%4];"
                 : "=r"(r[0]), "=r"(r[1]), "=r"(r[2]), "=r"(r[3]) : "r"(a));
}
__device__ __forceinline__ void mma16816(float* c, const u32* a, u32 b0, u32 b1) {
    asm volatile(
        "mma.sync.aligned.m16n8k16.row.col.f32.bf16.bf16.f32 "
        "{%0,%1,%2,%3}, {%4,%5,%6,%7}, {%8,%9}, {%0,%1,%2,%3};"
        : "+f"(c[0]), "+f"(c[1]), "+f"(c[2]), "+f"(c[3])
        : "r"(a[0]), "r"(a[1]), "r"(a[2]), "r"(a[3]), "r"(b0), "r"(b1));
}
__device__ __forceinline__ void split2(float a, float b, u32& hi, u32& lo) {
    __nv_bfloat162 h = __floats2bfloat162_rn(a, b);
    float ha = __bfloat162float(h.x), hb = __bfloat162float(h.y);
    __nv_bfloat162 l = __floats2bfloat162_rn(a - ha, b - hb);
    hi = *reinterpret_cast<u32*>(&h);
    lo = *reinterpret_cast<u32*>(&l);
}

// ===========================================================================
// K_INIT (one launch, 66 blocks):
//  blocks 0..63: flag reset + h1 row b = relu(x@W1+b1) + its bf16 A-image row
//  block 64:     Wg1 bf16 image
//  block 65:     layer-2 collapse vectors
// ===========================================================================
__global__ void k_init(const float* __restrict__ x,
                       const float* __restrict__ W1,
                       const float* __restrict__ b1,
                       const float* __restrict__ Wg1,
                       const float* __restrict__ Wg2,
                       const float* __restrict__ Wout,
                       const float* __restrict__ g2,
                       const float* __restrict__ b2ln) {
    const int bx = blockIdx.x;
    const int j  = threadIdx.x;
    if (bx < 64) {
        if (j < 32) g_flag[bx * 32 + j] = 0;
        __shared__ float sx[ENC_IN];
        __shared__ float sh[ENC_HID];
        if (j < ENC_IN) sx[j] = x[bx * ENC_IN + j];
        __syncthreads();
        float acc = b1[j];
#pragma unroll
        for (int k = 0; k < ENC_IN; k++)
            acc = fmaf(sx[k], W1[k * ENC_HID + j], acc);
        float h = fmaxf(acc, 0.0f);
        g_h1[bx * ENC_HID + j] = h;
        sh[j] = h;
        __syncthreads();
        if (j < 128) {
            u32 hi, lo;
            split2(sh[2 * j], sh[2 * j + 1], hi, lo);
            g_AH[bx * 132 + j] = hi;
            g_AL[bx * 132 + j] = lo;
        }
    } else if (bx == 64) {
        if (j < GHD) {
            for (int k = 0; k < GHD; k += 2) {
                u32 hi, lo;
                split2(Wg1[k * GHD + j], Wg1[(k + 1) * GHD + j], hi, lo);
                g_BH[j * 68 + (k >> 1)] = hi;
                g_BL[j * 68 + (k >> 1)] = lo;
            }
        }
    } else {
        __shared__ float sr1[GHD], sr2[GHD];
        if (j < GHD) {
            float w2o = 0.0f;
            for (int d = 0; d < GHD; d++)
                w2o = fmaf(Wg2[j * GHD + d], Wout[d], w2o);
            float gwv = g2[j] * w2o;
            g_gw[j] = gwv;
            sr1[j] = gwv;
            sr2[j] = b2ln[j] * w2o;
        }
        __syncthreads();
        if (j == 0) {
            float k1 = 0.0f, k2 = 0.0f;
            for (int i = 0; i < GHD; i++) { k1 += sr1[i]; k2 += sr2[i]; }
            g_K[0] = k1;
            g_K[1] = k2;
        }
    }
}

// ===========================================================================
// K_MEGA: dispatch-ordered roles.
//  [0, 2048):    enc role — enc(:, bx, :) = h1 @ W2[:, bx*128..] + b2,
//                then set g_flag[bx].
//  [2048, 3136): gcn role — wait on its tile's node flags, then fused GCN
//                layer-1 GEMM + collapsed layer-2 + projection.
// ===========================================================================
// enc-role smem offsets
#define ESB       528
#define EBB       272
#define E_AHI     0
#define E_ALO     33792
#define E_BHI     67584
#define E_BLO     76288
// gcn-role smem offsets
#define GSB       272
#define G_AHI     0
#define G_ALO     34816
#define G_RB      69632                    // B-half hi staging / C tile
#define G_RLO     87040                    // B-half lo staging
#define G_SMEM    104448

__global__ __launch_bounds__(256, 2) void k_mega(const float* __restrict__ W2,
                                                 const float* __restrict__ b2,
                                                 const float* __restrict__ Ah,
                                                 const float* __restrict__ g1,
                                                 const float* __restrict__ bb1,
                                                 const float* __restrict__ Wout,
                                                 const float* __restrict__ bout,
                                                 float* __restrict__ proj) {
    const int tid = threadIdx.x;
    const int L   = tid & 31;
    const int w   = tid >> 5;
    const u32 sb  = smem_u32(dynsm);

    if (blockIdx.x < N_ENC_BLK) {
        // ================= enc role =================
        const int j0 = blockIdx.x * 128;

        // ---- stage A image (linear uint4 copies; layout pre-baked) ----
        {
            uint4* dh = (uint4*)(dynsm + E_AHI);
            uint4* dl = (uint4*)(dynsm + E_ALO);
            const uint4* shp = (const uint4*)g_AH;
            const uint4* slp = (const uint4*)g_AL;
            for (int i = tid; i < 2112; i += 256) {
                dh[i] = shp[i];
                dl[i] = slp[i];
            }
        }

        const int mw = w & 1, nw = w >> 1;
        const int R0 = mw * 32, N0 = nw * 32;
        const u32 arow = (u32)(L & 15);
        const u32 kcol = (u32)((L >> 4) << 3);
        const u32 brow = (u32)((L & 7) + ((L >> 3) & 1) * 8);
        const u32 bcol = (u32)((L >> 4) << 3);

        float acc[2][4][4];
#pragma unroll
        for (int mt = 0; mt < 2; mt++)
#pragma unroll
            for (int j = 0; j < 4; j++)
#pragma unroll
                for (int c = 0; c < 4; c++) acc[mt][j][c] = 0.0f;

        float4 pf[4];
#pragma unroll
        for (int t = 0; t < 4; t++) {
            int i = tid + t * 256;
            int row = i >> 5, c4 = i & 31;
            pf[t] = *(const float4*)&W2[(size_t)row * JTOT + j0 + c4 * 4];
        }

        for (int kp = 0; kp < 8; kp++) {
            __syncthreads();
#pragma unroll
            for (int t = 0; t < 4; t++) {
                int i = tid + t * 256;
                int row = i >> 5, c4 = i & 31;
                u32 h0, l0, h1, l1;
                split2(pf[t].x, pf[t].y, h0, l0);
                split2(pf[t].z, pf[t].w, h1, l1);
                *(uint2*)(dynsm + E_BHI + row * EBB + c4 * 8) = make_uint2(h0, h1);
                *(uint2*)(dynsm + E_BLO + row * EBB + c4 * 8) = make_uint2(l0, l1);
            }
            __syncthreads();
            if (kp < 7) {
#pragma unroll
                for (int t = 0; t < 4; t++) {
                    int i = tid + t * 256;
                    int row = i >> 5, c4 = i & 31;
                    pf[t] = *(const float4*)&W2[(size_t)((kp + 1) * 32 + row) * JTOT +
                                                j0 + c4 * 4];
                }
            }

#pragma unroll
            for (int p = 0; p < 3; p++) {
                const u32 aOff = (p < 2) ? E_AHI : E_ALO;
                const u32 bOff = (p == 1) ? E_BLO : E_BHI;
#pragma unroll
                for (int ks = 0; ks < 2; ks++) {
                    u32 a0[4], a1[4];
                    u32 ka = (u32)((kp * 32 + ks * 16 + kcol) * 2);
                    ldsm4(a0, sb + aOff + (R0 + arow) * ESB + ka);
                    ldsm4(a1, sb + aOff + (R0 + 16 + arow) * ESB + ka);
                    u32 bf[2][4];
                    u32 kb = (u32)((ks * 16 + brow) * EBB);
#pragma unroll
                    for (int nt = 0; nt < 2; nt++)
                        ldsm4t(bf[nt], sb + bOff + kb + (N0 + nt * 16 + bcol) * 2);
#pragma unroll
                    for (int j = 0; j < 4; j++) {
                        u32 b0 = bf[j >> 1][(j & 1) * 2];
                        u32 b1 = bf[j >> 1][(j & 1) * 2 + 1];
                        mma16816(acc[0][j], a0, b0, b1);
                        mma16816(acc[1][j], a1, b0, b1);
                    }
                }
            }
        }

#pragma unroll
        for (int mt = 0; mt < 2; mt++) {
            int m = R0 + mt * 16 + (L >> 2);
#pragma unroll
            for (int j = 0; j < 4; j++) {
                int n = j0 + N0 + j * 8 + (L & 3) * 2;
                float b20 = __ldg(&b2[n]), b21 = __ldg(&b2[n + 1]);
                *(float2*)&g_buf0[(size_t)m * JTOT + n] =
                    make_float2(acc[mt][j][0] + b20, acc[mt][j][1] + b21);
                *(float2*)&g_buf0[(size_t)(m + 8) * JTOT + n] =
                    make_float2(acc[mt][j][2] + b20, acc[mt][j][3] + b21);
            }
        }

        // ---- publish: node blockIdx.x is complete ----
        __threadfence();
        __syncthreads();
        if (tid == 0) ((volatile int*)g_flag)[blockIdx.x] = 1;
        return;
    }

    // ================= gcn role =================
    __shared__ float sAp[128], sAn[128];
    __shared__ float sG1[128], sB1[128], sWo[128], sGw[128];
    __shared__ float sP[128][4];
    __shared__ float sT[128], sU[128];

    const int bx = blockIdx.x - N_ENC_BLK;
    const int nt = bx >> 6;                // 0..16
    const int b  = bx & 63;
    const int n0 = nt * 124;               // staged row r <-> gi = n0 - 2 + r

    if (tid < 128) {
        sG1[tid] = g1[tid];
        sB1[tid] = bb1[tid];
        sWo[tid] = Wout[tid];
        sGw[tid] = g_gw[tid];
        int gi = n0 - 2 + tid;
        sAp[tid] = (gi >= 1 && gi < NNODES) ? Ah[(size_t)gi * NNODES + gi - 1] : 0.0f;
        sAn[tid] = (gi >= 0 && gi < NNODES - 1) ? Ah[(size_t)gi * NNODES + gi + 1] : 0.0f;
    }

    // ---- stage B half 0 (no dependency on enc output) ----
    {
        uint4* dh = (uint4*)(dynsm + G_RB);
        uint4* dl = (uint4*)(dynsm + G_RLO);
        for (int i = tid; i < 1088; i += 256) {
            dh[i] = ((const uint4*)g_BH)[i];
            dl[i] = ((const uint4*)g_BL)[i];
        }
    }

    // ---- wait for the nodes this tile reads ----
    if (tid < 128) {
        int gi = min(NNODES - 1, max(0, n0 - 2 + tid));
        while (((volatile int*)g_flag)[gi] == 0) __nanosleep(128);
    }
    __threadfence();
    __syncthreads();

    // ---- LN1 + bf16 split -> A tiles (warp w owns rows {w+8t}) ----
    const int c0 = 2 * L, c2 = 64 + 2 * L;
#pragma unroll 4
    for (int t = 0; t < 16; t++) {
        int row = w + 8 * t;
        int gi  = min(NNODES - 1, max(0, n0 - 2 + row));
        const float* p = &g_buf0[((size_t)b * NNODES + gi) * GHD + c0];
        float2 v0 = *(const float2*)p;
        float2 v1 = *(const float2*)(p + 64);
        float s = v0.x + v0.y + v1.x + v1.y;
        float q = v0.x * v0.x + v0.y * v0.y + v1.x * v1.x + v1.y * v1.y;
#pragma unroll
        for (int o = 16; o; o >>= 1) {
            s += __shfl_xor_sync(0xFFFFFFFFu, s, o);
            q += __shfl_xor_sync(0xFFFFFFFFu, q, o);
        }
        float mu   = s * (1.0f / GHD);
        float rstd = rsqrtf(fmaxf(q * (1.0f / GHD) - mu * mu, 0.0f) + LN_EPS);
        float f0 = (v0.x - mu) * rstd * sG1[c0] + sB1[c0];
        float f1 = (v0.y - mu) * rstd * sG1[c0 + 1] + sB1[c0 + 1];
        float f2 = (v1.x - mu) * rstd * sG1[c2] + sB1[c2];
        float f3 = (v1.y - mu) * rstd * sG1[c2 + 1] + sB1[c2 + 1];
        u32 h0, l0, h1, l1;
        split2(f0, f1, h0, l0);
        split2(f2, f3, h1, l1);
        *(u32*)(dynsm + G_AHI + row * GSB + L * 4)       = h0;
        *(u32*)(dynsm + G_AHI + row * GSB + 128 + L * 4) = h1;
        *(u32*)(dynsm + G_ALO + row * GSB + L * 4)       = l0;
        *(u32*)(dynsm + G_ALO + row * GSB + 128 + L * 4) = l1;
    }
    __syncthreads();

    const int mw = w & 3, nh = w >> 2;
    const int R0 = mw * 32, N0 = nh * 32;
    const u32 arow = (u32)(L & 15);
    const u32 kcol = (u32)((L >> 4) << 3);
    float* sC = (float*)(dynsm + G_RB);
    const float K1 = g_K[0], K2 = g_K[1];

    for (int h = 0; h < 2; h++) {
        if (h) {
            uint4* dh = (uint4*)(dynsm + G_RB);
            uint4* dl = (uint4*)(dynsm + G_RLO);
            for (int i = tid; i < 1088; i += 256) {
                dh[i] = ((const uint4*)g_BH)[1088 + i];
                dl[i] = ((const uint4*)g_BL)[1088 + i];
            }
            __syncthreads();
        }

        // ---- MMA: 128M x 64N, 3-pass bf16 split (warp tile 32x32) ----
        float acc[2][4][4];
#pragma unroll
        for (int mt = 0; mt < 2; mt++)
#pragma unroll
            for (int j = 0; j < 4; j++)
#pragma unroll
                for (int c = 0; c < 4; c++) acc[mt][j][c] = 0.0f;

#pragma unroll
        for (int p = 0; p < 3; p++) {
            const u32 aOff = (p < 2) ? G_AHI : G_ALO;
            const u32 bOff = (p == 1) ? (u32)G_RLO : (u32)G_RB;
#pragma unroll
            for (int ks = 0; ks < 8; ks++) {
                u32 kb = (u32)((ks * 16 + kcol) * 2);
                u32 a0[4], a1[4];
                ldsm4(a0, sb + aOff + (R0 + arow) * GSB + kb);
                ldsm4(a1, sb + aOff + (R0 + 16 + arow) * GSB + kb);
                u32 bf[2][4];
#pragma unroll
                for (int nth = 0; nth < 2; nth++)
                    ldsm4(bf[nth], sb + bOff + (N0 + nth * 16 + arow) * GSB + kb);
#pragma unroll
                for (int j = 0; j < 4; j++) {
                    u32 b0 = bf[j >> 1][(j & 1)];
                    u32 b1 = bf[j >> 1][(j & 1) + 2];
                    mma16816(acc[0][j], a0, b0, b1);
                    mma16816(acc[1][j], a1, b0, b1);
                }
            }
        }
        __syncthreads();

        // ---- C frags -> sC ----
#pragma unroll
        for (int mt = 0; mt < 2; mt++) {
            int m = R0 + mt * 16 + (L >> 2);
#pragma unroll
            for (int j = 0; j < 4; j++) {
                int n = N0 + j * 8 + (L & 3) * 2;
                *(float2*)&sC[m * 68 + n] =
                    make_float2(acc[mt][j][0], acc[mt][j][1]);
                *(float2*)&sC[(m + 8) * 68 + n] =
                    make_float2(acc[mt][j][2], acc[mt][j][3]);
            }
        }
        __syncthreads();

        // ---- dot pass: out1 cols of this half -> 4 partial dots per row ----
        const int cg = h * 64 + 2 * L;
#pragma unroll 2
        for (int t = 0; t < 16; t++) {
            int row = w + 8 * t;
            if (row < 1 || row > 126) continue;
            int gi = min(NNODES - 1, max(0, n0 - 2 + row));
            float2 iv = *(const float2*)&g_buf0[((size_t)b * NNODES + gi) * GHD + cg];
            float2 wp = *(const float2*)&sC[(row - 1) * 68 + 2 * L];
            float2 wn = *(const float2*)&sC[(row + 1) * 68 + 2 * L];
            float ap = sAp[row], an = sAn[row];
            float o0 = fmaf(an, wn.x, fmaf(ap, wp.x, iv.x));
            float o1 = fmaf(an, wn.y, fmaf(ap, wp.y, iv.y));
            float sv = o0 + o1;
            float sq = o0 * o0 + o1 * o1;
            float st = o0 * sWo[cg] + o1 * sWo[cg + 1];
            float sg = o0 * sGw[cg] + o1 * sGw[cg + 1];
#pragma unroll
            for (int o = 16; o; o >>= 1) {
                sv += __shfl_xor_sync(0xFFFFFFFFu, sv, o);
                sq += __shfl_xor_sync(0xFFFFFFFFu, sq, o);
                st += __shfl_xor_sync(0xFFFFFFFFu, st, o);
                sg += __shfl_xor_sync(0xFFFFFFFFu, sg, o);
            }
            if (L == 0) {
                if (h == 0) {
                    sP[row][0] = sv; sP[row][1] = sq;
                    sP[row][2] = st; sP[row][3] = sg;
                } else {
                    sv += sP[row][0];
                    sq += sP[row][1];
                    st += sP[row][2];
                    sg += sP[row][3];
                    float mu   = sv * (1.0f / GHD);
                    float rstd = rsqrtf(fmaxf(sq * (1.0f / GHD) - mu * mu, 0.0f) +
                                        LN_EPS);
                    sT[row] = st;
                    sU[row] = rstd * (sg - mu * K1) + K2;
                }
            }
        }
        __syncthreads();
    }

    // ---- final: rows 2..125 -> proj ----
    if (tid < 124) {
        int row = tid + 2;
        int gi  = n0 + tid;
        if (gi < NNODES) {
            float f = sT[row] + sAp[row] * sU[row - 1] + sAn[row] * sU[row + 1] +
                      bout[0];
            proj[b * NNODES + gi] = f;
        }
    }
}

// ===========================================================================
extern "C" void kernel_launch(void* const* d_in, const int* in_sizes, int n_in,
                              void* d_out, int out_size) {
    const float* x    = (const float*)d_in[0];
    const float* Ah   = (const float*)d_in[1];
    const float* W1   = (const float*)d_in[2];
    const float* b1   = (const float*)d_in[3];
    const float* W2   = (const float*)d_in[4];
    const float* b2   = (const float*)d_in[5];
    const float* Wg1  = (const float*)d_in[6];
    const float* Wg2  = (const float*)d_in[7];
    const float* g1   = (const float*)d_in[8];
    const float* bb1  = (const float*)d_in[9];
    const float* g2   = (const float*)d_in[10];
    const float* bb2  = (const float*)d_in[11];
    const float* Wout = (const float*)d_in[12];
    const float* bout = (const float*)d_in[13];
    float* out = (float*)d_out;

    cudaFuncSetAttribute(k_mega, cudaFuncAttributeMaxDynamicSharedMemorySize,
                         G_SMEM);

    k_init<<<66, ENC_HID>>>(x, W1, b1, Wg1, Wg2, Wout, g2, bb2);
    k_mega<<<N_ENC_BLK + N_GCN_BLK, 256, G_SMEM>>>(W2, b2, Ah, g1, bb1,
                                                   Wout, bout, out);
}

// round 11
// speedup vs baseline: 1.4861x; 1.1612x over previous
#include <cuda_runtime.h>
#include <cuda_bf16.h>

typedef unsigned int       u32;
typedef unsigned long long u64;

#define BSZ      64
#define ENC_IN   64
#define ENC_HID  256
#define NNODES   2048
#define GHD      128
#define JTOT     (NNODES * GHD)      // 262144
#define LN_EPS   1e-5f

#define N_ENC_BLK NNODES             // 2048 (one node per enc block)
#define N_GCN_BLK (17 * BSZ)         // 1088

// ---------------- scratch (device globals: allocation-guard safe) ----------
__device__ float g_h1[BSZ * ENC_HID];                  // [m][k] h1 rows
__device__ float g_buf0[(size_t)BSZ * NNODES * GHD];   // enc output
// A (=h1) bf16 hi/lo smem-image, row stride 528B (132 u32), 64 rows
__device__ __align__(16) u32 g_AH[64 * 132];
__device__ __align__(16) u32 g_AL[64 * 132];
// Wg1 transposed [n][k] bf16 hi/lo image, row stride 136 halfs (= 68 u32)
__device__ __align__(16) u32 g_BH[GHD * 68];
__device__ __align__(16) u32 g_BL[GHD * 68];
// layer-2 collapse: w2o = Wg2 @ Wout; gw = g2*w2o; K = {sum gw, sum b2*w2o}
__device__ float g_gw[GHD];
__device__ float g_K[2];
// per-node completion flags for producer/consumer safety
__device__ int g_flag[NNODES];

extern __shared__ __align__(1024) char dynsm[];

// ---------------- helpers ---------------------------------------------------
__device__ __forceinline__ u32 smem_u32(const void* p) {
    u32 a;
    asm("{ .reg .u64 t; cvta.to.shared.u64 t, %1; cvt.u32.u64 %0, t; }"
        : "=r"(a) : "l"(p));
    return a;
}
__device__ __forceinline__ void ldsm4(u32* r, u32 a) {
    asm volatile("ldmatrix.sync.aligned.m8n8.x4.shared.b16 {%0,%1,%2,%3}, [%4];"
                 : "=r"(r[0]), "=r"(r[1]), "=r"(r[2]), "=r"(r[3]) : "r"(a));
}
__device__ __forceinline__ void ldsm4t(u32* r, u32 a) {
    asm volatile("ldmatrix.sync.aligned.m8n8.x4.trans.shared.b16 {%0,%1,%2,%3}, [%4];"
                 : "=r"(r[0]), "=r"(r[1]), "=r"(r[2]), "=r"(r[3]) : "r"(a));
}
__device__ __forceinline__ void mma16816(float* c, const u32* a, u32 b0, u32 b1) {
    asm volatile(
        "mma.sync.aligned.m16n8k16.row.col.f32.bf16.bf16.f32 "
        "{%0,%1,%2,%3}, {%4,%5,%6,%7}, {%8,%9}, {%0,%1,%2,%3};"
        : "+f"(c[0]), "+f"(c[1]), "+f"(c[2]), "+f"(c[3])
        : "r"(a[0]), "r"(a[1]), "r"(a[2]), "r"(a[3]), "r"(b0), "r"(b1));
}
__device__ __forceinline__ void split2(float a, float b, u32& hi, u32& lo) {
    __nv_bfloat162 h = __floats2bfloat162_rn(a, b);
    float ha = __bfloat162float(h.x), hb = __bfloat162float(h.y);
    __nv_bfloat162 l = __floats2bfloat162_rn(a - ha, b - hb);
    hi = *reinterpret_cast<u32*>(&h);
    lo = *reinterpret_cast<u32*>(&l);
}

// ===========================================================================
// K_INIT (one launch, 66 blocks):
//  blocks 0..63: flag reset + h1 row b = relu(x@W1+b1) + its bf16 A-image row
//  block 64:     Wg1 bf16 image
//  block 65:     layer-2 collapse vectors
// ===========================================================================
__global__ void k_init(const float* __restrict__ x,
                       const float* __restrict__ W1,
                       const float* __restrict__ b1,
                       const float* __restrict__ Wg1,
                       const float* __restrict__ Wg2,
                       const float* __restrict__ Wout,
                       const float* __restrict__ g2,
                       const float* __restrict__ b2ln) {
    const int bx = blockIdx.x;
    const int j  = threadIdx.x;
    if (bx < 64) {
        if (j < 32) g_flag[bx * 32 + j] = 0;
        __shared__ float sx[ENC_IN];
        __shared__ float sh[ENC_HID];
        if (j < ENC_IN) sx[j] = x[bx * ENC_IN + j];
        __syncthreads();
        float acc = b1[j];
#pragma unroll
        for (int k = 0; k < ENC_IN; k++)
            acc = fmaf(sx[k], W1[k * ENC_HID + j], acc);
        float h = fmaxf(acc, 0.0f);
        g_h1[bx * ENC_HID + j] = h;
        sh[j] = h;
        __syncthreads();
        if (j < 128) {
            u32 hi, lo;
            split2(sh[2 * j], sh[2 * j + 1], hi, lo);
            g_AH[bx * 132 + j] = hi;
            g_AL[bx * 132 + j] = lo;
        }
    } else if (bx == 64) {
        if (j < GHD) {
            for (int k = 0; k < GHD; k += 2) {
                u32 hi, lo;
                split2(Wg1[k * GHD + j], Wg1[(k + 1) * GHD + j], hi, lo);
                g_BH[j * 68 + (k >> 1)] = hi;
                g_BL[j * 68 + (k >> 1)] = lo;
            }
        }
    } else {
        __shared__ float sr1[GHD], sr2[GHD];
        if (j < GHD) {
            float w2o = 0.0f;
            for (int d = 0; d < GHD; d++)
                w2o = fmaf(Wg2[j * GHD + d], Wout[d], w2o);
            float gwv = g2[j] * w2o;
            g_gw[j] = gwv;
            sr1[j] = gwv;
            sr2[j] = b2ln[j] * w2o;
        }
        __syncthreads();
        if (j == 0) {
            float k1 = 0.0f, k2 = 0.0f;
            for (int i = 0; i < GHD; i++) { k1 += sr1[i]; k2 += sr2[i]; }
            g_K[0] = k1;
            g_K[1] = k2;
        }
    }
}

// ===========================================================================
// K_MEGA: dispatch-ordered roles.
//  [0, 2048):    enc role — enc(:, bx, :) = h1 @ W2[:, bx*128..] + b2,
//                then set g_flag[bx].
//  [2048, 3136): gcn role — wait on its tile's node flags, then fused GCN
//                layer-1 GEMM (B-image-major pass order, full-N) +
//                collapsed layer-2 + projection.
// ===========================================================================
// enc-role smem offsets
#define ESB       528
#define EBB       272
#define E_AHI     0
#define E_ALO     33792
#define E_BHI     67584
#define E_BLO     76288
// gcn-role smem offsets
#define GSB       272
#define G_AHI     0
#define G_ALO     34816
#define G_BREG    69632                    // full-N B image (hi, then lo) / C in A region
#define G_SMEM    104448

__global__ __launch_bounds__(256, 2) void k_mega(const float* __restrict__ W2,
                                                 const float* __restrict__ b2,
                                                 const float* __restrict__ Ah,
                                                 const float* __restrict__ g1,
                                                 const float* __restrict__ bb1,
                                                 const float* __restrict__ Wout,
                                                 const float* __restrict__ bout,
                                                 float* __restrict__ proj) {
    const int tid = threadIdx.x;
    const int L   = tid & 31;
    const int w   = tid >> 5;
    const u32 sb  = smem_u32(dynsm);

    if (blockIdx.x < N_ENC_BLK) {
        // ================= enc role (unchanged from R10) =================
        const int j0 = blockIdx.x * 128;

        {
            uint4* dh = (uint4*)(dynsm + E_AHI);
            uint4* dl = (uint4*)(dynsm + E_ALO);
            const uint4* shp = (const uint4*)g_AH;
            const uint4* slp = (const uint4*)g_AL;
            for (int i = tid; i < 2112; i += 256) {
                dh[i] = shp[i];
                dl[i] = slp[i];
            }
        }

        const int mw = w & 1, nw = w >> 1;
        const int R0 = mw * 32, N0 = nw * 32;
        const u32 arow = (u32)(L & 15);
        const u32 kcol = (u32)((L >> 4) << 3);
        const u32 brow = (u32)((L & 7) + ((L >> 3) & 1) * 8);
        const u32 bcol = (u32)((L >> 4) << 3);

        float acc[2][4][4];
#pragma unroll
        for (int mt = 0; mt < 2; mt++)
#pragma unroll
            for (int j = 0; j < 4; j++)
#pragma unroll
                for (int c = 0; c < 4; c++) acc[mt][j][c] = 0.0f;

        float4 pf[4];
#pragma unroll
        for (int t = 0; t < 4; t++) {
            int i = tid + t * 256;
            int row = i >> 5, c4 = i & 31;
            pf[t] = *(const float4*)&W2[(size_t)row * JTOT + j0 + c4 * 4];
        }

        for (int kp = 0; kp < 8; kp++) {
            __syncthreads();
#pragma unroll
            for (int t = 0; t < 4; t++) {
                int i = tid + t * 256;
                int row = i >> 5, c4 = i & 31;
                u32 h0, l0, h1, l1;
                split2(pf[t].x, pf[t].y, h0, l0);
                split2(pf[t].z, pf[t].w, h1, l1);
                *(uint2*)(dynsm + E_BHI + row * EBB + c4 * 8) = make_uint2(h0, h1);
                *(uint2*)(dynsm + E_BLO + row * EBB + c4 * 8) = make_uint2(l0, l1);
            }
            __syncthreads();
            if (kp < 7) {
#pragma unroll
                for (int t = 0; t < 4; t++) {
                    int i = tid + t * 256;
                    int row = i >> 5, c4 = i & 31;
                    pf[t] = *(const float4*)&W2[(size_t)((kp + 1) * 32 + row) * JTOT +
                                                j0 + c4 * 4];
                }
            }

#pragma unroll
            for (int p = 0; p < 3; p++) {
                const u32 aOff = (p < 2) ? E_AHI : E_ALO;
                const u32 bOff = (p == 1) ? E_BLO : E_BHI;
#pragma unroll
                for (int ks = 0; ks < 2; ks++) {
                    u32 a0[4], a1[4];
                    u32 ka = (u32)((kp * 32 + ks * 16 + kcol) * 2);
                    ldsm4(a0, sb + aOff + (R0 + arow) * ESB + ka);
                    ldsm4(a1, sb + aOff + (R0 + 16 + arow) * ESB + ka);
                    u32 bf[2][4];
                    u32 kb = (u32)((ks * 16 + brow) * EBB);
#pragma unroll
                    for (int nt = 0; nt < 2; nt++)
                        ldsm4t(bf[nt], sb + bOff + kb + (N0 + nt * 16 + bcol) * 2);
#pragma unroll
                    for (int j = 0; j < 4; j++) {
                        u32 b0 = bf[j >> 1][(j & 1) * 2];
                        u32 b1 = bf[j >> 1][(j & 1) * 2 + 1];
                        mma16816(acc[0][j], a0, b0, b1);
                        mma16816(acc[1][j], a1, b0, b1);
                    }
                }
            }
        }

#pragma unroll
        for (int mt = 0; mt < 2; mt++) {
            int m = R0 + mt * 16 + (L >> 2);
#pragma unroll
            for (int j = 0; j < 4; j++) {
                int n = j0 + N0 + j * 8 + (L & 3) * 2;
                float b20 = __ldg(&b2[n]), b21 = __ldg(&b2[n + 1]);
                *(float2*)&g_buf0[(size_t)m * JTOT + n] =
                    make_float2(acc[mt][j][0] + b20, acc[mt][j][1] + b21);
                *(float2*)&g_buf0[(size_t)(m + 8) * JTOT + n] =
                    make_float2(acc[mt][j][2] + b20, acc[mt][j][3] + b21);
            }
        }

        __threadfence();
        __syncthreads();
        if (tid == 0) ((volatile int*)g_flag)[blockIdx.x] = 1;
        return;
    }

    // ================= gcn role =================
    __shared__ float sAp[128], sAn[128];
    __shared__ float sG1[128], sB1[128], sWo[128], sGw[128];
    __shared__ float sT[128], sU[128];

    const int bx = blockIdx.x - N_ENC_BLK;
    const int nt = bx >> 6;                // 0..16
    const int b  = bx & 63;
    const int n0 = nt * 124;               // staged row r <-> gi = n0 - 2 + r

    if (tid < 128) {
        sG1[tid] = g1[tid];
        sB1[tid] = bb1[tid];
        sWo[tid] = Wout[tid];
        sGw[tid] = g_gw[tid];
        int gi = n0 - 2 + tid;
        sAp[tid] = (gi >= 1 && gi < NNODES) ? Ah[(size_t)gi * NNODES + gi - 1] : 0.0f;
        sAn[tid] = (gi >= 0 && gi < NNODES - 1) ? Ah[(size_t)gi * NNODES + gi + 1] : 0.0f;
    }

    // ---- stage Bhi full-N (no dependency on enc output) ----
    {
        uint4* dh = (uint4*)(dynsm + G_BREG);
        for (int i = tid; i < 2176; i += 256)
            dh[i] = ((const uint4*)g_BH)[i];
    }

    // ---- wait for the nodes this tile reads ----
    if (tid < 128) {
        int gi = min(NNODES - 1, max(0, n0 - 2 + tid));
        while (((volatile int*)g_flag)[gi] == 0) __nanosleep(128);
    }
    __threadfence();
    __syncthreads();

    // ---- LN1 + bf16 split -> A tiles (warp w owns rows {w+8t}) ----
    const int c0 = 2 * L, c2 = 64 + 2 * L;
#pragma unroll 4
    for (int t = 0; t < 16; t++) {
        int row = w + 8 * t;
        int gi  = min(NNODES - 1, max(0, n0 - 2 + row));
        const float* p = &g_buf0[((size_t)b * NNODES + gi) * GHD + c0];
        float2 v0 = *(const float2*)p;
        float2 v1 = *(const float2*)(p + 64);
        float s = v0.x + v0.y + v1.x + v1.y;
        float q = v0.x * v0.x + v0.y * v0.y + v1.x * v1.x + v1.y * v1.y;
#pragma unroll
        for (int o = 16; o; o >>= 1) {
            s += __shfl_xor_sync(0xFFFFFFFFu, s, o);
            q += __shfl_xor_sync(0xFFFFFFFFu, q, o);
        }
        float mu   = s * (1.0f / GHD);
        float rstd = rsqrtf(fmaxf(q * (1.0f / GHD) - mu * mu, 0.0f) + LN_EPS);
        float f0 = (v0.x - mu) * rstd * sG1[c0] + sB1[c0];
        float f1 = (v0.y - mu) * rstd * sG1[c0 + 1] + sB1[c0 + 1];
        float f2 = (v1.x - mu) * rstd * sG1[c2] + sB1[c2];
        float f3 = (v1.y - mu) * rstd * sG1[c2 + 1] + sB1[c2 + 1];
        u32 h0, l0, h1, l1;
        split2(f0, f1, h0, l0);
        split2(f2, f3, h1, l1);
        *(u32*)(dynsm + G_AHI + row * GSB + L * 4)       = h0;
        *(u32*)(dynsm + G_AHI + row * GSB + 128 + L * 4) = h1;
        *(u32*)(dynsm + G_ALO + row * GSB + L * 4)       = l0;
        *(u32*)(dynsm + G_ALO + row * GSB + 128 + L * 4) = l1;
    }
    __syncthreads();

    // ---- MMA: full N=128, B-image-major pass order ----
    // warp tile: 32M x 64N (two 32-N subtiles at N0 and N0+64)
    const int mw = w & 3, nh = w >> 2;
    const int R0 = mw * 32;
    const u32 arow = (u32)(L & 15);
    const u32 kcol = (u32)((L >> 4) << 3);
    const float K1 = g_K[0], K2 = g_K[1];

    float acc[2][2][4][4];                 // [ns][mt][j][c]
#pragma unroll
    for (int ns = 0; ns < 2; ns++)
#pragma unroll
        for (int mt = 0; mt < 2; mt++)
#pragma unroll
            for (int j = 0; j < 4; j++)
#pragma unroll
                for (int c = 0; c < 4; c++) acc[ns][mt][j][c] = 0.0f;

    // Phase 1: (Ahi + Alo) * Bhi
#pragma unroll
    for (int ks = 0; ks < 8; ks++) {
        u32 kb = (u32)((ks * 16 + kcol) * 2);
        u32 ah0[4], ah1[4], al0[4], al1[4];
        ldsm4(ah0, sb + G_AHI + (R0 + arow) * GSB + kb);
        ldsm4(ah1, sb + G_AHI + (R0 + 16 + arow) * GSB + kb);
        ldsm4(al0, sb + G_ALO + (R0 + arow) * GSB + kb);
        ldsm4(al1, sb + G_ALO + (R0 + 16 + arow) * GSB + kb);
#pragma unroll
        for (int ns = 0; ns < 2; ns++) {
            int N0 = nh * 32 + ns * 64;
            u32 bf[2][4];
#pragma unroll
            for (int g = 0; g < 2; g++)
                ldsm4(bf[g], sb + G_BREG + (N0 + g * 16 + arow) * GSB + kb);
#pragma unroll
            for (int j = 0; j < 4; j++) {
                u32 b0 = bf[j >> 1][(j & 1)];
                u32 b1 = bf[j >> 1][(j & 1) + 2];
                mma16816(acc[ns][0][j], ah0, b0, b1);
                mma16816(acc[ns][1][j], ah1, b0, b1);
                mma16816(acc[ns][0][j], al0, b0, b1);
                mma16816(acc[ns][1][j], al1, b0, b1);
            }
        }
    }
    __syncthreads();                       // Bhi reads done -> restage as Blo
    {
        uint4* dh = (uint4*)(dynsm + G_BREG);
        for (int i = tid; i < 2176; i += 256)
            dh[i] = ((const uint4*)g_BL)[i];
    }
    __syncthreads();

    // Phase 2: Ahi * Blo
#pragma unroll
    for (int ks = 0; ks < 8; ks++) {
        u32 kb = (u32)((ks * 16 + kcol) * 2);
        u32 ah0[4], ah1[4];
        ldsm4(ah0, sb + G_AHI + (R0 + arow) * GSB + kb);
        ldsm4(ah1, sb + G_AHI + (R0 + 16 + arow) * GSB + kb);
#pragma unroll
        for (int ns = 0; ns < 2; ns++) {
            int N0 = nh * 32 + ns * 64;
            u32 bf[2][4];
#pragma unroll
            for (int g = 0; g < 2; g++)
                ldsm4(bf[g], sb + G_BREG + (N0 + g * 16 + arow) * GSB + kb);
#pragma unroll
            for (int j = 0; j < 4; j++) {
                u32 b0 = bf[j >> 1][(j & 1)];
                u32 b1 = bf[j >> 1][(j & 1) + 2];
                mma16816(acc[ns][0][j], ah0, b0, b1);
                mma16816(acc[ns][1][j], ah1, b0, b1);
            }
        }
    }
    __syncthreads();                       // A reads done -> A region becomes C

    // ---- C frags -> sC (A region, stride 136 floats) ----
    float* sC = (float*)(dynsm + G_AHI);
#pragma unroll
    for (int ns = 0; ns < 2; ns++) {
#pragma unroll
        for (int mt = 0; mt < 2; mt++) {
            int m = R0 + mt * 16 + (L >> 2);
            int n = nh * 32 + ns * 64 + (L & 3) * 2;
#pragma unroll
            for (int j = 0; j < 4; j++) {
                *(float2*)&sC[m * 136 + n + j * 8] =
                    make_float2(acc[ns][mt][j][0], acc[ns][mt][j][1]);
                *(float2*)&sC[(m + 8) * 136 + n + j * 8] =
                    make_float2(acc[ns][mt][j][2], acc[ns][mt][j][3]);
            }
        }
    }
    __syncthreads();

    // ---- single full-width dot pass -> sT, sU ----
#pragma unroll 2
    for (int t = 0; t < 16; t++) {
        int row = w + 8 * t;
        if (row < 1 || row > 126) continue;
        int gi = min(NNODES - 1, max(0, n0 - 2 + row));
        const float* p = &g_buf0[((size_t)b * NNODES + gi) * GHD + c0];
        float2 iv0 = *(const float2*)p;
        float2 iv1 = *(const float2*)(p + 64);
        float2 wp0 = *(const float2*)&sC[(row - 1) * 136 + c0];
        float2 wp1 = *(const float2*)&sC[(row - 1) * 136 + c2];
        float2 wn0 = *(const float2*)&sC[(row + 1) * 136 + c0];
        float2 wn1 = *(const float2*)&sC[(row + 1) * 136 + c2];
        float ap = sAp[row], an = sAn[row];
        float o0 = fmaf(an, wn0.x, fmaf(ap, wp0.x, iv0.x));
        float o1 = fmaf(an, wn0.y, fmaf(ap, wp0.y, iv0.y));
        float o2 = fmaf(an, wn1.x, fmaf(ap, wp1.x, iv1.x));
        float o3 = fmaf(an, wn1.y, fmaf(ap, wp1.y, iv1.y));
        float sv = o0 + o1 + o2 + o3;
        float sq = o0 * o0 + o1 * o1 + o2 * o2 + o3 * o3;
        float st = o0 * sWo[c0] + o1 * sWo[c0 + 1] + o2 * sWo[c2] + o3 * sWo[c2 + 1];
        float sg = o0 * sGw[c0] + o1 * sGw[c0 + 1] + o2 * sGw[c2] + o3 * sGw[c2 + 1];
#pragma unroll
        for (int o = 16; o; o >>= 1) {
            sv += __shfl_xor_sync(0xFFFFFFFFu, sv, o);
            sq += __shfl_xor_sync(0xFFFFFFFFu, sq, o);
            st += __shfl_xor_sync(0xFFFFFFFFu, st, o);
            sg += __shfl_xor_sync(0xFFFFFFFFu, sg, o);
        }
        if (L == 0) {
            float mu   = sv * (1.0f / GHD);
            float rstd = rsqrtf(fmaxf(sq * (1.0f / GHD) - mu * mu, 0.0f) + LN_EPS);
            sT[row] = st;
            sU[row] = rstd * (sg - mu * K1) + K2;
        }
    }
    __syncthreads();

    // ---- final: rows 2..125 -> proj ----
    if (tid < 124) {
        int row = tid + 2;
        int gi  = n0 + tid;
        if (gi < NNODES) {
            float f = sT[row] + sAp[row] * sU[row - 1] + sAn[row] * sU[row + 1] +
                      bout[0];
            proj[b * NNODES + gi] = f;
        }
    }
}

// ===========================================================================
extern "C" void kernel_launch(void* const* d_in, const int* in_sizes, int n_in,
                              void* d_out, int out_size) {
    const float* x    = (const float*)d_in[0];
    const float* Ah   = (const float*)d_in[1];
    const float* W1   = (const float*)d_in[2];
    const float* b1   = (const float*)d_in[3];
    const float* W2   = (const float*)d_in[4];
    const float* b2   = (const float*)d_in[5];
    const float* Wg1  = (const float*)d_in[6];
    const float* Wg2  = (const float*)d_in[7];
    const float* g1   = (const float*)d_in[8];
    const float* bb1  = (const float*)d_in[9];
    const float* g2   = (const float*)d_in[10];
    const float* bb2  = (const float*)d_in[11];
    const float* Wout = (const float*)d_in[12];
    const float* bout = (const float*)d_in[13];
    float* out = (float*)d_out;

    cudaFuncSetAttribute(k_mega, cudaFuncAttributeMaxDynamicSharedMemorySize,
                         G_SMEM);

    k_init<<<66, ENC_HID>>>(x, W1, b1, Wg1, Wg2, Wout, g2, bb2);
    k_mega<<<N_ENC_BLK + N_GCN_BLK, 256, G_SMEM>>>(W2, b2, Ah, g1, bb1,
                                                   Wout, bout, out);
}

// round 12
// speedup vs baseline: 1.4882x; 1.0014x over previous
#include <cuda_runtime.h>
#include <cuda_bf16.h>

typedef unsigned int       u32;
typedef unsigned long long u64;

#define BSZ      64
#define ENC_IN   64
#define ENC_HID  256
#define NNODES   2048
#define GHD      128
#define JTOT     (NNODES * GHD)      // 262144
#define LN_EPS   1e-5f

#define N_ENC_BLK NNODES             // 2048 (one node per enc block)
#define N_GCN_BLK (17 * BSZ)         // 1088

// ---------------- scratch (device globals: allocation-guard safe) ----------
__device__ float g_h1[BSZ * ENC_HID];                  // [m][k] h1 rows
__device__ float g_buf0[(size_t)BSZ * NNODES * GHD];   // enc output
// A (=h1) bf16 hi/lo smem-image, row stride 528B (132 u32), 64 rows
__device__ __align__(16) u32 g_AH[64 * 132];
__device__ __align__(16) u32 g_AL[64 * 132];
// Wg1 transposed [n][k] bf16 hi/lo image, row stride 136 halfs (= 68 u32)
__device__ __align__(16) u32 g_BH[GHD * 68];
__device__ __align__(16) u32 g_BL[GHD * 68];
// layer-2 collapse: w2o = Wg2 @ Wout; gw = g2*w2o; K = {sum gw, sum b2*w2o}
__device__ float g_gw[GHD];
__device__ float g_K[2];
// per-node completion flags for producer/consumer safety
__device__ int g_flag[NNODES];

extern __shared__ __align__(1024) char dynsm[];

// ---------------- helpers ---------------------------------------------------
__device__ __forceinline__ u32 smem_u32(const void* p) {
    u32 a;
    asm("{ .reg .u64 t; cvta.to.shared.u64 t, %1; cvt.u32.u64 %0, t; }"
        : "=r"(a) : "l"(p));
    return a;
}
__device__ __forceinline__ void ldsm4(u32* r, u32 a) {
    asm volatile("ldmatrix.sync.aligned.m8n8.x4.shared.b16 {%0,%1,%2,%3}, [%4];"
                 : "=r"(r[0]), "=r"(r[1]), "=r"(r[2]), "=r"(r[3]) : "r"(a));
}
__device__ __forceinline__ void ldsm4t(u32* r, u32 a) {
    asm volatile("ldmatrix.sync.aligned.m8n8.x4.trans.shared.b16 {%0,%1,%2,%3}, [%4];"
                 : "=r"(r[0]), "=r"(r[1]), "=r"(r[2]), "=r"(r[3]) : "r"(a));
}
__device__ __forceinline__ void mma16816(float* c, const u32* a, u32 b0, u32 b1) {
    asm volatile(
        "mma.sync.aligned.m16n8k16.row.col.f32.bf16.bf16.f32 "
        "{%0,%1,%2,%3}, {%4,%5,%6,%7}, {%8,%9}, {%0,%1,%2,%3};"
        : "+f"(c[0]), "+f"(c[1]), "+f"(c[2]), "+f"(c[3])
        : "r"(a[0]), "r"(a[1]), "r"(a[2]), "r"(a[3]), "r"(b0), "r"(b1));
}
__device__ __forceinline__ void split2(float a, float b, u32& hi, u32& lo) {
    __nv_bfloat162 h = __floats2bfloat162_rn(a, b);
    float ha = __bfloat162float(h.x), hb = __bfloat162float(h.y);
    __nv_bfloat162 l = __floats2bfloat162_rn(a - ha, b - hb);
    hi = *reinterpret_cast<u32*>(&h);
    lo = *reinterpret_cast<u32*>(&l);
}

// ===========================================================================
// K_INIT (one launch, 66 blocks):
//  blocks 0..63: flag reset + h1 row b = relu(x@W1+b1) + its bf16 A-image row
//  block 64:     Wg1 bf16 image
//  block 65:     layer-2 collapse vectors
// ===========================================================================
__global__ void k_init(const float* __restrict__ x,
                       const float* __restrict__ W1,
                       const float* __restrict__ b1,
                       const float* __restrict__ Wg1,
                       const float* __restrict__ Wg2,
                       const float* __restrict__ Wout,
                       const float* __restrict__ g2,
                       const float* __restrict__ b2ln) {
    const int bx = blockIdx.x;
    const int j  = threadIdx.x;
    if (bx < 64) {
        if (j < 32) g_flag[bx * 32 + j] = 0;
        __shared__ float sx[ENC_IN];
        __shared__ float sh[ENC_HID];
        if (j < ENC_IN) sx[j] = x[bx * ENC_IN + j];
        __syncthreads();
        float acc = b1[j];
#pragma unroll
        for (int k = 0; k < ENC_IN; k++)
            acc = fmaf(sx[k], W1[k * ENC_HID + j], acc);
        float h = fmaxf(acc, 0.0f);
        g_h1[bx * ENC_HID + j] = h;
        sh[j] = h;
        __syncthreads();
        if (j < 128) {
            u32 hi, lo;
            split2(sh[2 * j], sh[2 * j + 1], hi, lo);
            g_AH[bx * 132 + j] = hi;
            g_AL[bx * 132 + j] = lo;
        }
    } else if (bx == 64) {
        if (j < GHD) {
            for (int k = 0; k < GHD; k += 2) {
                u32 hi, lo;
                split2(Wg1[k * GHD + j], Wg1[(k + 1) * GHD + j], hi, lo);
                g_BH[j * 68 + (k >> 1)] = hi;
                g_BL[j * 68 + (k >> 1)] = lo;
            }
        }
    } else {
        __shared__ float sr1[GHD], sr2[GHD];
        if (j < GHD) {
            float w2o = 0.0f;
            for (int d = 0; d < GHD; d++)
                w2o = fmaf(Wg2[j * GHD + d], Wout[d], w2o);
            float gwv = g2[j] * w2o;
            g_gw[j] = gwv;
            sr1[j] = gwv;
            sr2[j] = b2ln[j] * w2o;
        }
        __syncthreads();
        if (j == 0) {
            float k1 = 0.0f, k2 = 0.0f;
            for (int i = 0; i < GHD; i++) { k1 += sr1[i]; k2 += sr2[i]; }
            g_K[0] = k1;
            g_K[1] = k2;
        }
    }
}

// ===========================================================================
// K_MEGA: dispatch-ordered roles.
//  [0, 2048):    enc role — enc(:, bx, :) = h1 @ W2[:, bx*128..] + b2;
//                fused 3-pass MMA per k-step, double-buffered B panels
//                (1 sync per panel); sets g_flag[bx].
//  [2048, 3136): gcn role — wait on tile's node flags, then fused GCN
//                layer-1 GEMM (B-image-major, full-N) + collapsed layer-2.
// ===========================================================================
// enc-role smem offsets
#define ESB       528
#define EBB       272
#define E_AHI     0
#define E_ALO     33792
#define E_B0HI    67584
#define E_B0LO    76288
#define E_B1HI    84992
#define E_B1LO    93696
// gcn-role smem offsets
#define GSB       272
#define G_AHI     0
#define G_ALO     34816
#define G_BREG    69632                    // full-N B image (hi, then lo) / C in A region
#define G_SMEM    104448

__global__ __launch_bounds__(256, 2) void k_mega(const float* __restrict__ W2,
                                                 const float* __restrict__ b2,
                                                 const float* __restrict__ Ah,
                                                 const float* __restrict__ g1,
                                                 const float* __restrict__ bb1,
                                                 const float* __restrict__ Wout,
                                                 const float* __restrict__ bout,
                                                 float* __restrict__ proj) {
    const int tid = threadIdx.x;
    const int L   = tid & 31;
    const int w   = tid >> 5;
    const u32 sb  = smem_u32(dynsm);

    if (blockIdx.x < N_ENC_BLK) {
        // ================= enc role =================
        const int j0 = blockIdx.x * 128;

        // ---- stage A image (linear uint4 copies; layout pre-baked) ----
        {
            uint4* dh = (uint4*)(dynsm + E_AHI);
            uint4* dl = (uint4*)(dynsm + E_ALO);
            const uint4* shp = (const uint4*)g_AH;
            const uint4* slp = (const uint4*)g_AL;
            for (int i = tid; i < 2112; i += 256) {
                dh[i] = shp[i];
                dl[i] = slp[i];
            }
        }

        const int mw = w & 1, nw = w >> 1;
        const int R0 = mw * 32, N0 = nw * 32;
        const u32 arow = (u32)(L & 15);
        const u32 kcol = (u32)((L >> 4) << 3);
        const u32 brow = (u32)((L & 7) + ((L >> 3) & 1) * 8);
        const u32 bcol = (u32)((L >> 4) << 3);

        float acc[2][4][4];
#pragma unroll
        for (int mt = 0; mt < 2; mt++)
#pragma unroll
            for (int j = 0; j < 4; j++)
#pragma unroll
                for (int c = 0; c < 4; c++) acc[mt][j][c] = 0.0f;

        // prefetch panel 0 (4 float4/thread: 32x128 floats)
        float4 pf[4], pf2[4];
#pragma unroll
        for (int t = 0; t < 4; t++) {
            int i = tid + t * 256;
            int row = i >> 5, c4 = i & 31;
            pf[t] = *(const float4*)&W2[(size_t)row * JTOT + j0 + c4 * 4];
        }

        for (int kp = 0; kp < 8; kp++) {
            const u32 bHI = (kp & 1) ? E_B1HI : E_B0HI;
            const u32 bLO = (kp & 1) ? E_B1LO : E_B0LO;
            // issue next panel's global loads first (hide latency under all below)
            if (kp < 7) {
#pragma unroll
                for (int t = 0; t < 4; t++) {
                    int i = tid + t * 256;
                    int row = i >> 5, c4 = i & 31;
                    pf2[t] = *(const float4*)&W2[(size_t)((kp + 1) * 32 + row) * JTOT +
                                                 j0 + c4 * 4];
                }
            }
            // convert current panel -> this stage (other stage may still be in MMA)
#pragma unroll
            for (int t = 0; t < 4; t++) {
                int i = tid + t * 256;
                int row = i >> 5, c4 = i & 31;
                u32 h0, l0, h1, l1;
                split2(pf[t].x, pf[t].y, h0, l0);
                split2(pf[t].z, pf[t].w, h1, l1);
                *(uint2*)(dynsm + bHI + row * EBB + c4 * 8) = make_uint2(h0, h1);
                *(uint2*)(dynsm + bLO + row * EBB + c4 * 8) = make_uint2(l0, l1);
            }
            __syncthreads();

            // ---- fused 3-pass MMA over this panel ----
#pragma unroll
            for (int ks = 0; ks < 2; ks++) {
                u32 ka = (u32)((kp * 32 + ks * 16 + kcol) * 2);
                u32 ah0[4], ah1[4], al0[4], al1[4];
                ldsm4(ah0, sb + E_AHI + (R0 + arow) * ESB + ka);
                ldsm4(ah1, sb + E_AHI + (R0 + 16 + arow) * ESB + ka);
                ldsm4(al0, sb + E_ALO + (R0 + arow) * ESB + ka);
                ldsm4(al1, sb + E_ALO + (R0 + 16 + arow) * ESB + ka);
                u32 kb = (u32)((ks * 16 + brow) * EBB);
                u32 bh[2][4], bl[2][4];
#pragma unroll
                for (int nt = 0; nt < 2; nt++) {
                    ldsm4t(bh[nt], sb + bHI + kb + (N0 + nt * 16 + bcol) * 2);
                    ldsm4t(bl[nt], sb + bLO + kb + (N0 + nt * 16 + bcol) * 2);
                }
#pragma unroll
                for (int j = 0; j < 4; j++) {
                    u32 b0 = bh[j >> 1][(j & 1) * 2];
                    u32 b1 = bh[j >> 1][(j & 1) * 2 + 1];
                    mma16816(acc[0][j], ah0, b0, b1);
                    mma16816(acc[1][j], ah1, b0, b1);
                    mma16816(acc[0][j], al0, b0, b1);
                    mma16816(acc[1][j], al1, b0, b1);
                    u32 c0v = bl[j >> 1][(j & 1) * 2];
                    u32 c1v = bl[j >> 1][(j & 1) * 2 + 1];
                    mma16816(acc[0][j], ah0, c0v, c1v);
                    mma16816(acc[1][j], ah1, c0v, c1v);
                }
            }
#pragma unroll
            for (int t = 0; t < 4; t++) pf[t] = pf2[t];
        }

#pragma unroll
        for (int mt = 0; mt < 2; mt++) {
            int m = R0 + mt * 16 + (L >> 2);
#pragma unroll
            for (int j = 0; j < 4; j++) {
                int n = j0 + N0 + j * 8 + (L & 3) * 2;
                float b20 = __ldg(&b2[n]), b21 = __ldg(&b2[n + 1]);
                *(float2*)&g_buf0[(size_t)m * JTOT + n] =
                    make_float2(acc[mt][j][0] + b20, acc[mt][j][1] + b21);
                *(float2*)&g_buf0[(size_t)(m + 8) * JTOT + n] =
                    make_float2(acc[mt][j][2] + b20, acc[mt][j][3] + b21);
            }
        }

        __threadfence();
        __syncthreads();
        if (tid == 0) ((volatile int*)g_flag)[blockIdx.x] = 1;
        return;
    }

    // ================= gcn role (unchanged from R11) =================
    __shared__ float sAp[128], sAn[128];
    __shared__ float sG1[128], sB1[128], sWo[128], sGw[128];
    __shared__ float sT[128], sU[128];

    const int bx = blockIdx.x - N_ENC_BLK;
    const int nt = bx >> 6;                // 0..16
    const int b  = bx & 63;
    const int n0 = nt * 124;               // staged row r <-> gi = n0 - 2 + r

    if (tid < 128) {
        sG1[tid] = g1[tid];
        sB1[tid] = bb1[tid];
        sWo[tid] = Wout[tid];
        sGw[tid] = g_gw[tid];
        int gi = n0 - 2 + tid;
        sAp[tid] = (gi >= 1 && gi < NNODES) ? Ah[(size_t)gi * NNODES + gi - 1] : 0.0f;
        sAn[tid] = (gi >= 0 && gi < NNODES - 1) ? Ah[(size_t)gi * NNODES + gi + 1] : 0.0f;
    }

    // ---- stage Bhi full-N (no dependency on enc output) ----
    {
        uint4* dh = (uint4*)(dynsm + G_BREG);
        for (int i = tid; i < 2176; i += 256)
            dh[i] = ((const uint4*)g_BH)[i];
    }

    // ---- wait for the nodes this tile reads ----
    if (tid < 128) {
        int gi = min(NNODES - 1, max(0, n0 - 2 + tid));
        while (((volatile int*)g_flag)[gi] == 0) __nanosleep(128);
    }
    __threadfence();
    __syncthreads();

    // ---- LN1 + bf16 split -> A tiles (warp w owns rows {w+8t}) ----
    const int c0 = 2 * L, c2 = 64 + 2 * L;
#pragma unroll 4
    for (int t = 0; t < 16; t++) {
        int row = w + 8 * t;
        int gi  = min(NNODES - 1, max(0, n0 - 2 + row));
        const float* p = &g_buf0[((size_t)b * NNODES + gi) * GHD + c0];
        float2 v0 = *(const float2*)p;
        float2 v1 = *(const float2*)(p + 64);
        float s = v0.x + v0.y + v1.x + v1.y;
        float q = v0.x * v0.x + v0.y * v0.y + v1.x * v1.x + v1.y * v1.y;
#pragma unroll
        for (int o = 16; o; o >>= 1) {
            s += __shfl_xor_sync(0xFFFFFFFFu, s, o);
            q += __shfl_xor_sync(0xFFFFFFFFu, q, o);
        }
        float mu   = s * (1.0f / GHD);
        float rstd = rsqrtf(fmaxf(q * (1.0f / GHD) - mu * mu, 0.0f) + LN_EPS);
        float f0 = (v0.x - mu) * rstd * sG1[c0] + sB1[c0];
        float f1 = (v0.y - mu) * rstd * sG1[c0 + 1] + sB1[c0 + 1];
        float f2 = (v1.x - mu) * rstd * sG1[c2] + sB1[c2];
        float f3 = (v1.y - mu) * rstd * sG1[c2 + 1] + sB1[c2 + 1];
        u32 h0, l0, h1, l1;
        split2(f0, f1, h0, l0);
        split2(f2, f3, h1, l1);
        *(u32*)(dynsm + G_AHI + row * GSB + L * 4)       = h0;
        *(u32*)(dynsm + G_AHI + row * GSB + 128 + L * 4) = h1;
        *(u32*)(dynsm + G_ALO + row * GSB + L * 4)       = l0;
        *(u32*)(dynsm + G_ALO + row * GSB + 128 + L * 4) = l1;
    }
    __syncthreads();

    // ---- MMA: full N=128, B-image-major pass order ----
    const int mw = w & 3, nh = w >> 2;
    const int R0 = mw * 32;
    const u32 arow = (u32)(L & 15);
    const u32 kcol = (u32)((L >> 4) << 3);
    const float K1 = g_K[0], K2 = g_K[1];

    float acc[2][2][4][4];                 // [ns][mt][j][c]
#pragma unroll
    for (int ns = 0; ns < 2; ns++)
#pragma unroll
        for (int mt = 0; mt < 2; mt++)
#pragma unroll
            for (int j = 0; j < 4; j++)
#pragma unroll
                for (int c = 0; c < 4; c++) acc[ns][mt][j][c] = 0.0f;

    // Phase 1: (Ahi + Alo) * Bhi
#pragma unroll
    for (int ks = 0; ks < 8; ks++) {
        u32 kb = (u32)((ks * 16 + kcol) * 2);
        u32 ah0[4], ah1[4], al0[4], al1[4];
        ldsm4(ah0, sb + G_AHI + (R0 + arow) * GSB + kb);
        ldsm4(ah1, sb + G_AHI + (R0 + 16 + arow) * GSB + kb);
        ldsm4(al0, sb + G_ALO + (R0 + arow) * GSB + kb);
        ldsm4(al1, sb + G_ALO + (R0 + 16 + arow) * GSB + kb);
#pragma unroll
        for (int ns = 0; ns < 2; ns++) {
            int N0 = nh * 32 + ns * 64;
            u32 bf[2][4];
#pragma unroll
            for (int g = 0; g < 2; g++)
                ldsm4(bf[g], sb + G_BREG + (N0 + g * 16 + arow) * GSB + kb);
#pragma unroll
            for (int j = 0; j < 4; j++) {
                u32 b0 = bf[j >> 1][(j & 1)];
                u32 b1 = bf[j >> 1][(j & 1) + 2];
                mma16816(acc[ns][0][j], ah0, b0, b1);
                mma16816(acc[ns][1][j], ah1, b0, b1);
                mma16816(acc[ns][0][j], al0, b0, b1);
                mma16816(acc[ns][1][j], al1, b0, b1);
            }
        }
    }
    __syncthreads();                       // Bhi reads done -> restage as Blo
    {
        uint4* dh = (uint4*)(dynsm + G_BREG);
        for (int i = tid; i < 2176; i += 256)
            dh[i] = ((const uint4*)g_BL)[i];
    }
    __syncthreads();

    // Phase 2: Ahi * Blo
#pragma unroll
    for (int ks = 0; ks < 8; ks++) {
        u32 kb = (u32)((ks * 16 + kcol) * 2);
        u32 ah0[4], ah1[4];
        ldsm4(ah0, sb + G_AHI + (R0 + arow) * GSB + kb);
        ldsm4(ah1, sb + G_AHI + (R0 + 16 + arow) * GSB + kb);
#pragma unroll
        for (int ns = 0; ns < 2; ns++) {
            int N0 = nh * 32 + ns * 64;
            u32 bf[2][4];
#pragma unroll
            for (int g = 0; g < 2; g++)
                ldsm4(bf[g], sb + G_BREG + (N0 + g * 16 + arow) * GSB + kb);
#pragma unroll
            for (int j = 0; j < 4; j++) {
                u32 b0 = bf[j >> 1][(j & 1)];
                u32 b1 = bf[j >> 1][(j & 1) + 2];
                mma16816(acc[ns][0][j], ah0, b0, b1);
                mma16816(acc[ns][1][j], ah1, b0, b1);
            }
        }
    }
    __syncthreads();                       // A reads done -> A region becomes C

    // ---- C frags -> sC (A region, stride 136 floats) ----
    float* sC = (float*)(dynsm + G_AHI);
#pragma unroll
    for (int ns = 0; ns < 2; ns++) {
#pragma unroll
        for (int mt = 0; mt < 2; mt++) {
            int m = R0 + mt * 16 + (L >> 2);
            int n = nh * 32 + ns * 64 + (L & 3) * 2;
#pragma unroll
            for (int j = 0; j < 4; j++) {
                *(float2*)&sC[m * 136 + n + j * 8] =
                    make_float2(acc[ns][mt][j][0], acc[ns][mt][j][1]);
                *(float2*)&sC[(m + 8) * 136 + n + j * 8] =
                    make_float2(acc[ns][mt][j][2], acc[ns][mt][j][3]);
            }
        }
    }
    __syncthreads();

    // ---- single full-width dot pass -> sT, sU ----
#pragma unroll 2
    for (int t = 0; t < 16; t++) {
        int row = w + 8 * t;
        if (row < 1 || row > 126) continue;
        int gi = min(NNODES - 1, max(0, n0 - 2 + row));
        const float* p = &g_buf0[((size_t)b * NNODES + gi) * GHD + c0];
        float2 iv0 = *(const float2*)p;
        float2 iv1 = *(const float2*)(p + 64);
        float2 wp0 = *(const float2*)&sC[(row - 1) * 136 + c0];
        float2 wp1 = *(const float2*)&sC[(row - 1) * 136 + c2];
        float2 wn0 = *(const float2*)&sC[(row + 1) * 136 + c0];
        float2 wn1 = *(const float2*)&sC[(row + 1) * 136 + c2];
        float ap = sAp[row], an = sAn[row];
        float o0 = fmaf(an, wn0.x, fmaf(ap, wp0.x, iv0.x));
        float o1 = fmaf(an, wn0.y, fmaf(ap, wp0.y, iv0.y));
        float o2 = fmaf(an, wn1.x, fmaf(ap, wp1.x, iv1.x));
        float o3 = fmaf(an, wn1.y, fmaf(ap, wp1.y, iv1.y));
        float sv = o0 + o1 + o2 + o3;
        float sq = o0 * o0 + o1 * o1 + o2 * o2 + o3 * o3;
        float st = o0 * sWo[c0] + o1 * sWo[c0 + 1] + o2 * sWo[c2] + o3 * sWo[c2 + 1];
        float sg = o0 * sGw[c0] + o1 * sGw[c0 + 1] + o2 * sGw[c2] + o3 * sGw[c2 + 1];
#pragma unroll
        for (int o = 16; o; o >>= 1) {
            sv += __shfl_xor_sync(0xFFFFFFFFu, sv, o);
            sq += __shfl_xor_sync(0xFFFFFFFFu, sq, o);
            st += __shfl_xor_sync(0xFFFFFFFFu, st, o);
            sg += __shfl_xor_sync(0xFFFFFFFFu, sg, o);
        }
        if (L == 0) {
            float mu   = sv * (1.0f / GHD);
            float rstd = rsqrtf(fmaxf(sq * (1.0f / GHD) - mu * mu, 0.0f) + LN_EPS);
            sT[row] = st;
            sU[row] = rstd * (sg - mu * K1) + K2;
        }
    }
    __syncthreads();

    // ---- final: rows 2..125 -> proj ----
    if (tid < 124) {
        int row = tid + 2;
        int gi  = n0 + tid;
        if (gi < NNODES) {
            float f = sT[row] + sAp[row] * sU[row - 1] + sAn[row] * sU[row + 1] +
                      bout[0];
            proj[b * NNODES + gi] = f;
        }
    }
}

// ===========================================================================
extern "C" void kernel_launch(void* const* d_in, const int* in_sizes, int n_in,
                              void* d_out, int out_size) {
    const float* x    = (const float*)d_in[0];
    const float* Ah   = (const float*)d_in[1];
    const float* W1   = (const float*)d_in[2];
    const float* b1   = (const float*)d_in[3];
    const float* W2   = (const float*)d_in[4];
    const float* b2   = (const float*)d_in[5];
    const float* Wg1  = (const float*)d_in[6];
    const float* Wg2  = (const float*)d_in[7];
    const float* g1   = (const float*)d_in[8];
    const float* bb1  = (const float*)d_in[9];
    const float* g2   = (const float*)d_in[10];
    const float* bb2  = (const float*)d_in[11];
    const float* Wout = (const float*)d_in[12];
    const float* bout = (const float*)d_in[13];
    float* out = (float*)d_out;

    cudaFuncSetAttribute(k_mega, cudaFuncAttributeMaxDynamicSharedMemorySize,
                         G_SMEM);

    k_init<<<66, ENC_HID>>>(x, W1, b1, Wg1, Wg2, Wout, g2, bb2);
    k_mega<<<N_ENC_BLK + N_GCN_BLK, 256, G_SMEM>>>(W2, b2, Ah, g1, bb1,
                                                   Wout, bout, out);
}